// round 5
// baseline (speedup 1.0000x reference)
#include <cuda_runtime.h>
#include <math.h>

#define THREADS 256
#define MAXN 4096
#define NB1 1024        // first-pass bins (top 10 bits of key)
#define SH1 22          // 32 - 10

// Order-preserving float->uint key: monotonic increasing with float value.
__device__ __forceinline__ unsigned f2key(float v) {
    unsigned u = __float_as_uint(v);
    return u ^ (unsigned)(((int)u >> 31) | 0x80000000u);
}
__device__ __forceinline__ float key2f(unsigned key) {
    unsigned u = (key & 0x80000000u) ? (key ^ 0x80000000u) : ~key;
    return __uint_as_float(u);
}

// Warp-collective: find bin containing the krem-th element (DESC = count from
// top bin downward, else from bottom upward). Returns bin index + residual rank.
template<int NB, bool DESC>
__device__ __forceinline__ void resolve(const unsigned* __restrict__ hist, int krem,
                                        int lane, unsigned &bin, int &krem_out)
{
    constexpr int BPL = NB / 32;
    unsigned s = 0;
    #pragma unroll 8
    for (int j = 0; j < BPL; j++) {
        int b = DESC ? (NB - 1 - (lane * BPL + j)) : (lane * BPL + j);
        s += hist[b];
    }
    unsigned p = s;
    #pragma unroll
    for (int o = 1; o < 32; o <<= 1) {
        unsigned t = __shfl_up_sync(0xFFFFFFFFu, p, o);
        if (lane >= o) p += t;
    }
    unsigned excl = p - s;
    bool cross = (excl < (unsigned)krem) && (p >= (unsigned)krem);
    unsigned m = __ballot_sync(0xFFFFFFFFu, cross);
    int src = __ffs(m) - 1;
    unsigned bsel = 0; int k2 = 0;
    if (lane == src) {
        unsigned cum = excl;
        #pragma unroll 8
        for (int j = 0; j < BPL; j++) {
            int b = DESC ? (NB - 1 - (lane * BPL + j)) : (lane * BPL + j);
            unsigned c = hist[b];
            if (cum + c >= (unsigned)krem) { bsel = (unsigned)b; k2 = krem - (int)cum; break; }
            cum += c;
        }
    }
    bin = __shfl_sync(0xFFFFFFFFu, bsel, src);
    krem_out = __shfl_sync(0xFFFFFFFFu, k2, src);
}

// Warp-aggregated append of one element index to a compaction list.
// pred: this thread has a candidate. Returns nothing; writes s_cand via leader atomic.
__device__ __forceinline__ void agg_append(bool pred, int idx, int lane,
                                           int* cnt, unsigned short* listbase,
                                           int dir /*+1 fwd, -1 bwd*/)
{
    unsigned bm = __ballot_sync(0xFFFFFFFFu, pred);
    if (pred) {
        int leader = __ffs(bm) - 1;
        int bbase;
        if (lane == leader) bbase = atomicAdd(cnt, __popc(bm));
        bbase = __shfl_sync(bm, bbase, leader);
        int r = bbase + __popc(bm & ((1u << lane) - 1u));
        listbase[dir > 0 ? r : -r] = (unsigned short)idx;
    }
}

__global__ void __launch_bounds__(THREADS, 8)
wildcat_kernel(const float* __restrict__ x, float* __restrict__ out,
               int n, int kmax, int kmin, float alpha)
{
    __shared__ float          s_x[MAXN];
    __shared__ unsigned short s_cand[MAXN];   // H grows from 0, L from MAXN-1
    __shared__ unsigned       s_hist[NB1];    // L1: 1024 bins; sub-levels: [0:256)=H,[256:512)=L
    __shared__ unsigned       s_selH, s_selL;
    __shared__ int            s_kremH, s_kremL;
    __shared__ int            s_cntH, s_cntL;
    __shared__ float          s_red[2][THREADS / 32];

    const int tid  = threadIdx.x;
    const int lane = tid & 31;
    const int wid  = tid >> 5;
    const long long row = blockIdx.x;
    const float* __restrict__ xr = x + row * (long long)n;

    // ---- init (vectorized hist clear) ----
    {
        uint4* h4 = (uint4*)s_hist;
        h4[tid] = make_uint4(0, 0, 0, 0);     // 256 * 16B = 4096B = NB1 bins
    }
    if (tid == 0) { s_cntH = 0; s_cntL = 0; }
    __syncthreads();

    // ================= pass 1: vectorized load + 10-bit histogram =============
    const int n4 = n >> 2;
    const float4* __restrict__ xr4 = (const float4*)xr;
    float4* sx4 = (float4*)s_x;
    const int nv4 = (n4 / THREADS) * THREADS;
    for (int i = tid; i < nv4; i += THREADS) {
        float4 v = xr4[i];
        sx4[i] = v;
        atomicAdd(&s_hist[f2key(v.x) >> SH1], 1u);
        atomicAdd(&s_hist[f2key(v.y) >> SH1], 1u);
        atomicAdd(&s_hist[f2key(v.z) >> SH1], 1u);
        atomicAdd(&s_hist[f2key(v.w) >> SH1], 1u);
    }
    for (int i = nv4 * 4 + tid; i < n; i += THREADS) {   // tail (none for n=4096)
        float v = xr[i];
        s_x[i] = v;
        atomicAdd(&s_hist[f2key(v) >> SH1], 1u);
    }
    __syncthreads();

    // ---- resolve level 0 (shared histogram; two warps in parallel) ----
    if (wid == 0) {
        unsigned b; int k2;
        resolve<NB1, true>(s_hist, kmax, lane, b, k2);
        if (lane == 0) { s_selH = b; s_kremH = k2; }
    } else if (wid == 1) {
        unsigned b; int k2;
        resolve<NB1, false>(s_hist, kmin, lane, b, k2);
        if (lane == 0) { s_selL = b; s_kremL = k2; }
    }
    __syncthreads();

    const unsigned binH = s_selH;
    const unsigned binL = s_selL;
    const bool sameBin = (binH == binL);

    // ===== pass 2: bulk sums + ballot-aggregated candidate compaction =========
    float sumT = 0.0f, sumB = 0.0f;
    for (int i = tid; i < nv4; i += THREADS) {
        float4 v = sx4[i];
        #pragma unroll
        for (int j = 0; j < 4; j++) {
            float f = (j == 0) ? v.x : (j == 1) ? v.y : (j == 2) ? v.z : v.w;
            unsigned b = f2key(f) >> SH1;
            if (b > binH) sumT += f;
            if (b < binL) sumB += f;
            agg_append(b == binH, 4 * i + j, lane, &s_cntH, s_cand, +1);
            if (!sameBin)
                agg_append(b == binL, 4 * i + j, lane, &s_cntL, s_cand + (MAXN - 1), -1);
        }
    }
    for (int i = nv4 * 4 + tid; i < n; i += THREADS) {   // tail
        float f = s_x[i];
        unsigned b = f2key(f) >> SH1;
        if (b > binH) sumT += f;
        if (b < binL) sumB += f;
        agg_append(b == binH, i, lane, &s_cntH, s_cand, +1);
        if (!sameBin)
            agg_append(b == binL, i, lane, &s_cntL, s_cand + (MAXN - 1), -1);
    }
    __syncthreads();

    const int cntH = s_cntH;
    const int cntL = sameBin ? cntH : s_cntL;

    // ===== 3 sub-levels over candidate lists ===================================
    // level bit layout: [31..22]=done, then 8, 8, 6 bit digits.
    #pragma unroll 1
    for (int lvl = 0; lvl < 3; lvl++) {
        s_hist[tid] = 0;
        s_hist[tid + 256] = 0;
        __syncthreads();
        const unsigned pH = s_selH;
        const unsigned pL = s_selL;
        const int fs = SH1 - 8 * lvl;                       // 22, 14, 6
        const int sh = (lvl < 2) ? (fs - 8) : 0;            // 14, 6, 0
        const unsigned mk = (lvl < 2) ? 0xFFu : 0x3Fu;
        const int dw = (lvl < 2) ? 8 : 6;

        for (int t = tid; t < cntH; t += THREADS) {
            unsigned key = f2key(s_x[s_cand[t]]);
            if ((key >> fs) == pH) atomicAdd(&s_hist[(key >> sh) & mk], 1u);
        }
        for (int t = tid; t < cntL; t += THREADS) {
            int idx = sameBin ? (int)s_cand[t] : (int)s_cand[MAXN - 1 - t];
            unsigned key = f2key(s_x[idx]);
            if ((key >> fs) == pL) atomicAdd(&s_hist[256 + ((key >> sh) & mk)], 1u);
        }
        __syncthreads();

        if (wid == 0) {
            unsigned b; int k2;
            resolve<256, true>(s_hist, s_kremH, lane, b, k2);
            if (lane == 0) { s_selH = (pH << dw) | b; s_kremH = k2; }
        } else if (wid == 1) {
            unsigned b; int k2;
            resolve<256, false>(s_hist + 256, s_kremL, lane, b, k2);
            if (lane == 0) { s_selL = (pL << dw) | b; s_kremL = k2; }
        }
        __syncthreads();
    }

    const unsigned keyH = s_selH;   // full 32-bit key of kth largest
    const unsigned keyL = s_selL;   // full 32-bit key of kth smallest

    // ===== tiny final sweep over candidates (strictly above / below) ==========
    for (int t = tid; t < cntH; t += THREADS) {
        float f = s_x[s_cand[t]];
        if (f2key(f) > keyH) sumT += f;
    }
    for (int t = tid; t < cntL; t += THREADS) {
        int idx = sameBin ? (int)s_cand[t] : (int)s_cand[MAXN - 1 - t];
        float f = s_x[idx];
        if (f2key(f) < keyL) sumB += f;
    }

    #pragma unroll
    for (int o = 16; o > 0; o >>= 1) {
        sumT += __shfl_xor_sync(0xFFFFFFFFu, sumT, o);
        sumB += __shfl_xor_sync(0xFFFFFFFFu, sumB, o);
    }
    if (lane == 0) { s_red[0][wid] = sumT; s_red[1][wid] = sumB; }
    __syncthreads();

    if (tid == 0) {
        float st = 0.0f, sb = 0.0f;
        #pragma unroll
        for (int w = 0; w < THREADS / 32; ++w) { st += s_red[0][w]; sb += s_red[1][w]; }
        st += (float)s_kremH * key2f(keyH);   // exact tie handling
        sb += (float)s_kremL * key2f(keyL);
        out[row] = st / (float)kmax + (alpha / (float)kmin) * sb;
    }
}

extern "C" void kernel_launch(void* const* d_in, const int* in_sizes, int n_in,
                              void* d_out, int out_size)
{
    const float* x = (const float*)d_in[0];
    float* out = (float*)d_out;

    const int rows = out_size;                 // 32*512 = 16384
    const int n = in_sizes[0] / rows;          // 4096
    int kmax = (int)lrintf(0.2f * (float)n);   // int(round(0.2*n)) = 819
    int kmin = (int)lrintf(0.2f * (float)n);
    if (kmax < 1) kmax = 1;
    if (kmin < 1) kmin = 1;

    wildcat_kernel<<<rows, THREADS>>>(x, out, n, kmax, kmin, 0.7f);
}

// round 6
// speedup vs baseline: 1.3743x; 1.3743x over previous
#include <cuda_runtime.h>
#include <math.h>

#define THREADS 256
#define MAXN 4096
#define NB1 1024        // first-pass bins (top 10 bits of key)
#define SH1 22          // 32 - 10

// Order-preserving float->uint key: monotonic increasing with float value.
__device__ __forceinline__ unsigned f2key(float v) {
    unsigned u = __float_as_uint(v);
    return u ^ (unsigned)(((int)u >> 31) | 0x80000000u);
}
__device__ __forceinline__ float key2f(unsigned key) {
    unsigned u = (key & 0x80000000u) ? (key ^ 0x80000000u) : ~key;
    return __uint_as_float(u);
}

// Warp-collective: find bin containing the krem-th element (DESC = count from
// top bin downward, else from bottom upward). Returns bin index + residual rank.
template<int NB, bool DESC>
__device__ __forceinline__ void resolve(const unsigned* __restrict__ hist, int krem,
                                        int lane, unsigned &bin, int &krem_out)
{
    constexpr int BPL = NB / 32;
    unsigned s = 0;
    #pragma unroll
    for (int j = 0; j < BPL; j++) {
        int b = DESC ? (NB - 1 - (lane * BPL + j)) : (lane * BPL + j);
        s += hist[b];
    }
    unsigned p = s;
    #pragma unroll
    for (int o = 1; o < 32; o <<= 1) {
        unsigned t = __shfl_up_sync(0xFFFFFFFFu, p, o);
        if (lane >= o) p += t;
    }
    unsigned excl = p - s;
    bool cross = (excl < (unsigned)krem) && (p >= (unsigned)krem);
    unsigned m = __ballot_sync(0xFFFFFFFFu, cross);
    int src = __ffs(m) - 1;
    unsigned bsel = 0; int k2 = 0;
    if (lane == src) {
        unsigned cum = excl;
        #pragma unroll
        for (int j = 0; j < BPL; j++) {
            int b = DESC ? (NB - 1 - (lane * BPL + j)) : (lane * BPL + j);
            unsigned c = hist[b];
            if (cum + c >= (unsigned)krem) { bsel = (unsigned)b; k2 = krem - (int)cum; break; }
            cum += c;
        }
    }
    bin = __shfl_sync(0xFFFFFFFFu, bsel, src);
    krem_out = __shfl_sync(0xFFFFFFFFu, k2, src);
}

__global__ void __launch_bounds__(THREADS, 8)
wildcat_kernel(const float* __restrict__ x, float* __restrict__ out,
               int n, int kmax, int kmin, float alpha)
{
    __shared__ float    s_val[MAXN];     // candidate VALUES: H grows from 0, L from MAXN-1
    __shared__ unsigned s_hist[NB1];     // L0: 1024 bins; sublevels: [0:256)=H, [256:512)=L
    __shared__ unsigned s_selH, s_selL;
    __shared__ int      s_kremH, s_kremL;
    __shared__ int      s_cntH, s_cntL;
    __shared__ float    s_red[2][THREADS / 32];

    const int tid  = threadIdx.x;
    const int lane = tid & 31;
    const int wid  = tid >> 5;
    const long long row = blockIdx.x;
    const float* __restrict__ xr = x + row * (long long)n;

    // ---- init ----
    ((uint4*)s_hist)[tid] = make_uint4(0, 0, 0, 0);   // clears all 1024 bins
    if (tid == 0) { s_cntH = 0; s_cntL = 0; }
    __syncthreads();

    const int n4 = n >> 2;
    const float4* __restrict__ xr4 = (const float4*)xr;
    const int nv4 = (n4 / THREADS) * THREADS;

    // ================= pass 1: gmem read + 10-bit histogram (no staging) ======
    for (int i = tid; i < nv4; i += THREADS) {
        float4 v = xr4[i];
        atomicAdd(&s_hist[f2key(v.x) >> SH1], 1u);
        atomicAdd(&s_hist[f2key(v.y) >> SH1], 1u);
        atomicAdd(&s_hist[f2key(v.z) >> SH1], 1u);
        atomicAdd(&s_hist[f2key(v.w) >> SH1], 1u);
    }
    for (int i = nv4 * 4 + tid; i < n; i += THREADS) {   // tail
        atomicAdd(&s_hist[f2key(xr[i]) >> SH1], 1u);
    }
    __syncthreads();

    // ---- resolve level 0 (two warps in parallel) ----
    if (wid == 0) {
        unsigned b; int k2;
        resolve<NB1, true>(s_hist, kmax, lane, b, k2);
        if (lane == 0) { s_selH = b; s_kremH = k2; }
    } else if (wid == 1) {
        unsigned b; int k2;
        resolve<NB1, false>(s_hist, kmin, lane, b, k2);
        if (lane == 0) { s_selL = b; s_kremL = k2; }
    }
    __syncthreads();

    const unsigned binH = s_selH;
    const unsigned binL = s_selL;
    const bool sameBin = (binH == binL);

    // clear the 512 sublevel bins
    s_hist[tid] = 0;
    s_hist[tid + 256] = 0;
    __syncthreads();

    // ===== pass 2: gmem re-read (L2 hit): bulk sums + value compaction ========
    //        + inline next-level (bits 21..14) histogram for candidates.
    float sumT = 0.0f, sumB = 0.0f;
    for (int i = tid; i < nv4; i += THREADS) {
        float4 v = xr4[i];
        #pragma unroll
        for (int j = 0; j < 4; j++) {
            float f = (j == 0) ? v.x : (j == 1) ? v.y : (j == 2) ? v.z : v.w;
            unsigned key = f2key(f);
            unsigned b = key >> SH1;
            if (b > binH) sumT += f;
            if (b < binL) sumB += f;
            if (b == binH) {
                int p = atomicAdd(&s_cntH, 1);
                s_val[p] = f;
                atomicAdd(&s_hist[(key >> 14) & 0xFFu], 1u);
            } else if (b == binL) {           // implies !sameBin
                int p = atomicAdd(&s_cntL, 1);
                s_val[MAXN - 1 - p] = f;
                atomicAdd(&s_hist[256 + ((key >> 14) & 0xFFu)], 1u);
            }
        }
    }
    for (int i = nv4 * 4 + tid; i < n; i += THREADS) {   // tail
        float f = xr[i];
        unsigned key = f2key(f);
        unsigned b = key >> SH1;
        if (b > binH) sumT += f;
        if (b < binL) sumB += f;
        if (b == binH) {
            int p = atomicAdd(&s_cntH, 1);
            s_val[p] = f;
            atomicAdd(&s_hist[(key >> 14) & 0xFFu], 1u);
        } else if (b == binL) {
            int p = atomicAdd(&s_cntL, 1);
            s_val[MAXN - 1 - p] = f;
            atomicAdd(&s_hist[256 + ((key >> 14) & 0xFFu)], 1u);
        }
    }
    __syncthreads();

    const int cntH = s_cntH;
    const int cntL = sameBin ? cntH : s_cntL;

    // ---- resolve level 1 (bits 21..14) ----
    if (wid == 0) {
        unsigned b; int k2;
        resolve<256, true>(s_hist, s_kremH, lane, b, k2);
        if (lane == 0) { s_selH = (binH << 8) | b; s_kremH = k2; }
    } else if (wid == 1) {
        unsigned b; int k2;
        resolve<256, false>(sameBin ? s_hist : (s_hist + 256), s_kremL, lane, b, k2);
        if (lane == 0) { s_selL = (binL << 8) | b; s_kremL = k2; }
    }
    __syncthreads();

    // ===== level 2 (bits 13..6) over candidate values ==========================
    {
        const unsigned pH = s_selH;
        const unsigned pL = s_selL;
        s_hist[tid] = 0;
        s_hist[tid + 256] = 0;
        __syncthreads();
        for (int t = tid; t < cntH; t += THREADS) {
            unsigned key = f2key(s_val[t]);
            if ((key >> 14) == pH) atomicAdd(&s_hist[(key >> 6) & 0xFFu], 1u);
        }
        for (int t = tid; t < cntL; t += THREADS) {
            float f = sameBin ? s_val[t] : s_val[MAXN - 1 - t];
            unsigned key = f2key(f);
            if ((key >> 14) == pL) atomicAdd(&s_hist[256 + ((key >> 6) & 0xFFu)], 1u);
        }
        __syncthreads();
        if (wid == 0) {
            unsigned b; int k2;
            resolve<256, true>(s_hist, s_kremH, lane, b, k2);
            if (lane == 0) { s_selH = (pH << 8) | b; s_kremH = k2; }
        } else if (wid == 1) {
            unsigned b; int k2;
            resolve<256, false>(s_hist + 256, s_kremL, lane, b, k2);
            if (lane == 0) { s_selL = (pL << 8) | b; s_kremL = k2; }
        }
        __syncthreads();
    }

    // ===== level 3 (bits 5..0, 64 bins) ========================================
    {
        const unsigned pH = s_selH;
        const unsigned pL = s_selL;
        if (tid < 128) { s_hist[tid] = 0; s_hist[tid + 256] = 0; }   // 64 used each side
        __syncthreads();
        for (int t = tid; t < cntH; t += THREADS) {
            unsigned key = f2key(s_val[t]);
            if ((key >> 6) == pH) atomicAdd(&s_hist[key & 0x3Fu], 1u);
        }
        for (int t = tid; t < cntL; t += THREADS) {
            float f = sameBin ? s_val[t] : s_val[MAXN - 1 - t];
            unsigned key = f2key(f);
            if ((key >> 6) == pL) atomicAdd(&s_hist[256 + (key & 0x3Fu)], 1u);
        }
        __syncthreads();
        if (wid == 0) {
            unsigned b; int k2;
            resolve<64, true>(s_hist, s_kremH, lane, b, k2);
            if (lane == 0) { s_selH = (pH << 6) | b; s_kremH = k2; }
        } else if (wid == 1) {
            unsigned b; int k2;
            resolve<64, false>(s_hist + 256, s_kremL, lane, b, k2);
            if (lane == 0) { s_selL = (pL << 6) | b; s_kremL = k2; }
        }
        __syncthreads();
    }

    const unsigned keyH = s_selH;   // full 32-bit key of kth largest
    const unsigned keyL = s_selL;   // full 32-bit key of kth smallest

    // ===== tiny final sweep over candidate values ==============================
    for (int t = tid; t < cntH; t += THREADS) {
        float f = s_val[t];
        if (f2key(f) > keyH) sumT += f;
    }
    for (int t = tid; t < cntL; t += THREADS) {
        float f = sameBin ? s_val[t] : s_val[MAXN - 1 - t];
        if (f2key(f) < keyL) sumB += f;
    }

    #pragma unroll
    for (int o = 16; o > 0; o >>= 1) {
        sumT += __shfl_xor_sync(0xFFFFFFFFu, sumT, o);
        sumB += __shfl_xor_sync(0xFFFFFFFFu, sumB, o);
    }
    if (lane == 0) { s_red[0][wid] = sumT; s_red[1][wid] = sumB; }
    __syncthreads();

    if (tid == 0) {
        float st = 0.0f, sb = 0.0f;
        #pragma unroll
        for (int w = 0; w < THREADS / 32; ++w) { st += s_red[0][w]; sb += s_red[1][w]; }
        st += (float)s_kremH * key2f(keyH);   // exact tie handling
        sb += (float)s_kremL * key2f(keyL);
        out[row] = st / (float)kmax + (alpha / (float)kmin) * sb;
    }
}

extern "C" void kernel_launch(void* const* d_in, const int* in_sizes, int n_in,
                              void* d_out, int out_size)
{
    const float* x = (const float*)d_in[0];
    float* out = (float*)d_out;

    const int rows = out_size;                 // 32*512 = 16384
    const int n = in_sizes[0] / rows;          // 4096
    int kmax = (int)lrintf(0.2f * (float)n);   // int(round(0.2*n)) = 819
    int kmin = (int)lrintf(0.2f * (float)n);
    if (kmax < 1) kmax = 1;
    if (kmin < 1) kmin = 1;

    wildcat_kernel<<<rows, THREADS>>>(x, out, n, kmax, kmin, 0.7f);
}